// round 1
// baseline (speedup 1.0000x reference)
#include <cuda_runtime.h>
#include <cuda_bf16.h>
#include <math.h>

// ---------------------------------------------------------------------------
// Problem constants
// ---------------------------------------------------------------------------
#define TOK      8192       // B*T tokens (4*2*1024)
#define IDIM     256
#define NU       512        // N_UNITS
#define EU       2048       // E_UNITS
#define NLAYERS  4
#define HEADS    8
#define DK       64
#define SEQ      1024
#define NBATCH   8          // bs*num

// ---------------------------------------------------------------------------
// Scratch (static device memory; allocation APIs are forbidden)
// ---------------------------------------------------------------------------
__device__ float g_e  [TOK * NU];
__device__ float g_q  [TOK * NU];
__device__ float g_k  [TOK * NU];
__device__ float g_v  [TOK * NU];
__device__ float g_ctx[TOK * NU];
__device__ float g_h  [TOK * EU];

// ---------------------------------------------------------------------------
// GEMM: C[M,N] = A[M,K] @ W[N,K]^T + bias (+ optional ReLU, + optional residual)
// 128x128 block tile, 16 K-slab, 8x8 register micro-tile, 256 threads.
// M,N,K are all multiples of the tile sizes for every call in this problem.
// ---------------------------------------------------------------------------
template<bool RELU, bool RES>
__global__ __launch_bounds__(256) void gemm_kernel(
    const float* __restrict__ A, const float* __restrict__ W,
    const float* __restrict__ bias, const float* __restrict__ res,
    float* __restrict__ C, int M, int N, int K)
{
    __shared__ float As[16][128];
    __shared__ float Ws[16][128];

    const int tid = threadIdx.x;
    const int tx  = tid & 15;        // 0..15 -> N direction
    const int ty  = tid >> 4;        // 0..15 -> M direction
    const int n0  = blockIdx.x * 128;
    const int m0  = blockIdx.y * 128;

    const float* Ap = A + (size_t)m0 * K;
    const float* Wp = W + (size_t)n0 * K;

    float acc[8][8];
#pragma unroll
    for (int i = 0; i < 8; i++)
#pragma unroll
        for (int j = 0; j < 8; j++) acc[i][j] = 0.0f;

    for (int k0 = 0; k0 < K; k0 += 16) {
        // cooperative load: 128x16 tiles of A and W, stored K-transposed
#pragma unroll
        for (int i = 0; i < 2; i++) {
            int idx = tid + i * 256;          // 0..511
            int r   = idx >> 2;               // 0..127
            int c4  = (idx & 3) * 4;          // 0,4,8,12
            float4 va = *(const float4*)(Ap + (size_t)r * K + k0 + c4);
            As[c4 + 0][r] = va.x; As[c4 + 1][r] = va.y;
            As[c4 + 2][r] = va.z; As[c4 + 3][r] = va.w;
            float4 vw = *(const float4*)(Wp + (size_t)r * K + k0 + c4);
            Ws[c4 + 0][r] = vw.x; Ws[c4 + 1][r] = vw.y;
            Ws[c4 + 2][r] = vw.z; Ws[c4 + 3][r] = vw.w;
        }
        __syncthreads();

#pragma unroll
        for (int kk = 0; kk < 16; kk++) {
            float a[8], b[8];
            *(float4*)&a[0] = *(const float4*)&As[kk][ty * 8];
            *(float4*)&a[4] = *(const float4*)&As[kk][ty * 8 + 4];
            *(float4*)&b[0] = *(const float4*)&Ws[kk][tx * 8];
            *(float4*)&b[4] = *(const float4*)&Ws[kk][tx * 8 + 4];
#pragma unroll
            for (int i = 0; i < 8; i++)
#pragma unroll
                for (int j = 0; j < 8; j++)
                    acc[i][j] += a[i] * b[j];
        }
        __syncthreads();
    }

    // epilogue
#pragma unroll
    for (int i = 0; i < 8; i++) {
        int m = m0 + ty * 8 + i;
#pragma unroll
        for (int j = 0; j < 8; j += 4) {
            int n = n0 + tx * 8 + j;
            float4 bv = *(const float4*)(bias + n);
            float4 o;
            o.x = acc[i][j + 0] + bv.x;
            o.y = acc[i][j + 1] + bv.y;
            o.z = acc[i][j + 2] + bv.z;
            o.w = acc[i][j + 3] + bv.w;
            if (RELU) {
                o.x = fmaxf(o.x, 0.0f); o.y = fmaxf(o.y, 0.0f);
                o.z = fmaxf(o.z, 0.0f); o.w = fmaxf(o.w, 0.0f);
            }
            if (RES) {
                float4 rv = *(const float4*)(res + (size_t)m * N + n);
                o.x += rv.x; o.y += rv.y; o.z += rv.z; o.w += rv.w;
            }
            *(float4*)(C + (size_t)m * N + n) = o;
        }
    }
}

// ---------------------------------------------------------------------------
// LayerNorm over rows of 512 (works in-place). 128 threads, float4 per thread.
// ---------------------------------------------------------------------------
__global__ __launch_bounds__(128) void ln_kernel(
    const float* __restrict__ X, const float* __restrict__ gamma,
    const float* __restrict__ beta, float* __restrict__ O)
{
    __shared__ float red[4];
    const int row = blockIdx.x;
    const int tid = threadIdx.x;

    float4 v = *(const float4*)(X + (size_t)row * NU + tid * 4);
    float s = v.x + v.y + v.z + v.w;
#pragma unroll
    for (int o = 16; o > 0; o >>= 1) s += __shfl_xor_sync(0xffffffffu, s, o);
    if ((tid & 31) == 0) red[tid >> 5] = s;
    __syncthreads();
    float mean = (red[0] + red[1] + red[2] + red[3]) * (1.0f / 512.0f);
    __syncthreads();

    float dx = v.x - mean, dy = v.y - mean, dz = v.z - mean, dw = v.w - mean;
    float sq = dx * dx + dy * dy + dz * dz + dw * dw;
#pragma unroll
    for (int o = 16; o > 0; o >>= 1) sq += __shfl_xor_sync(0xffffffffu, sq, o);
    if ((tid & 31) == 0) red[tid >> 5] = sq;
    __syncthreads();
    float var = (red[0] + red[1] + red[2] + red[3]) * (1.0f / 512.0f);
    float inv = rsqrtf(var + 1e-5f);

    float4 g = *(const float4*)(gamma + tid * 4);
    float4 b = *(const float4*)(beta  + tid * 4);
    float4 o4;
    o4.x = dx * inv * g.x + b.x;
    o4.y = dy * inv * g.y + b.y;
    o4.z = dz * inv * g.z + b.z;
    o4.w = dw * inv * g.w + b.w;
    *(float4*)(O + (size_t)row * NU + tid * 4) = o4;
}

// ---------------------------------------------------------------------------
// Attention: one block handles 8 query rows of one (b,h).
// Full 1024-wide score rows held in smem; K/V streamed in 32-row tiles.
// ---------------------------------------------------------------------------
__global__ __launch_bounds__(128) void attn_kernel(
    const float* __restrict__ Q, const float* __restrict__ K,
    const float* __restrict__ V, float* __restrict__ O)
{
    __shared__ float Ss[8][1024];     // scores / probs
    __shared__ float KVs[32][68];     // K or V tile (padded rows)
    __shared__ float rowsum[8];

    const int tid = threadIdx.x;
    const int qt = blockIdx.x;        // 0..127 (query tile of 8)
    const int h  = blockIdx.y;        // 0..7
    const int b  = blockIdx.z;        // 0..7
    const int qr = tid >> 4;          // 0..7  thread's query row
    const int sl = tid & 15;

    const size_t base = ((size_t)b * SEQ) * NU + (size_t)h * DK;

    // this thread's query row in registers (16 x float4 = 64 floats)
    float4 qreg[16];
    {
        const float* qp = Q + base + (size_t)(qt * 8 + qr) * NU;
#pragma unroll
        for (int i = 0; i < 16; i++) qreg[i] = *(const float4*)(qp + i * 4);
    }

    // ---- phase 1: scores = Q K^T * scale ----
    for (int st = 0; st < 32; st++) {
        int s0 = st * 32;
#pragma unroll
        for (int i = 0; i < 4; i++) {
            int idx = tid + i * 128;          // 0..511
            int r   = idx >> 4;               // 0..31
            int c4  = (idx & 15) * 4;         // 0..60
            *(float4*)&KVs[r][c4] =
                *(const float4*)(K + base + (size_t)(s0 + r) * NU + c4);
        }
        __syncthreads();
#pragma unroll
        for (int ss = 0; ss < 2; ss++) {
            int s = sl + ss * 16;
            float a = 0.0f;
#pragma unroll
            for (int i = 0; i < 16; i++) {
                float4 kk = *(const float4*)&KVs[s][i * 4];
                a += qreg[i].x * kk.x + qreg[i].y * kk.y
                   + qreg[i].z * kk.z + qreg[i].w * kk.w;
            }
            Ss[qr][s0 + s] = a * 0.125f;     // 1/sqrt(64)
        }
        __syncthreads();
    }

    // ---- phase 2: softmax (unnormalized; keep row sums) ----
    {
        const int warp = tid >> 5, lane = tid & 31;
        for (int r = warp; r < 8; r += 4) {
            float m = -1e30f;
            for (int j = lane; j < 1024; j += 32) m = fmaxf(m, Ss[r][j]);
#pragma unroll
            for (int o = 16; o > 0; o >>= 1)
                m = fmaxf(m, __shfl_xor_sync(0xffffffffu, m, o));
            float sum = 0.0f;
            for (int j = lane; j < 1024; j += 32) {
                float p = __expf(Ss[r][j] - m);
                Ss[r][j] = p;
                sum += p;
            }
#pragma unroll
            for (int o = 16; o > 0; o >>= 1)
                sum += __shfl_xor_sync(0xffffffffu, sum, o);
            if (lane == 0) rowsum[r] = sum;
        }
    }
    __syncthreads();

    // ---- phase 3: ctx = P V ----
    const int d0 = (tid & 15) * 4;
    float4 acc = make_float4(0.f, 0.f, 0.f, 0.f);
    for (int st = 0; st < 32; st++) {
        int s0 = st * 32;
#pragma unroll
        for (int i = 0; i < 4; i++) {
            int idx = tid + i * 128;
            int r   = idx >> 4;
            int c4  = (idx & 15) * 4;
            *(float4*)&KVs[r][c4] =
                *(const float4*)(V + base + (size_t)(s0 + r) * NU + c4);
        }
        __syncthreads();
#pragma unroll
        for (int s = 0; s < 32; s++) {
            float p = Ss[qr][s0 + s];
            float4 vv = *(const float4*)&KVs[s][d0];
            acc.x += p * vv.x; acc.y += p * vv.y;
            acc.z += p * vv.z; acc.w += p * vv.w;
        }
        __syncthreads();
    }

    float inv = 1.0f / rowsum[qr];
    float4 o4 = make_float4(acc.x * inv, acc.y * inv, acc.z * inv, acc.w * inv);
    *(float4*)(O + base + (size_t)(qt * 8 + qr) * NU + d0) = o4;
}

// ---------------------------------------------------------------------------
// Host orchestration (graph-capturable: kernel launches only)
// ---------------------------------------------------------------------------
extern "C" void kernel_launch(void* const* d_in, const int* in_sizes, int n_in,
                              void* d_out, int out_size)
{
    (void)in_sizes; (void)n_in; (void)out_size;

    const float* x     = (const float*)d_in[0];
    const float* Win   = (const float*)d_in[1];
    const float* bin   = (const float*)d_in[2];
    const float* ln1_g = (const float*)d_in[3];
    const float* ln1_b = (const float*)d_in[4];
    const float* Wq    = (const float*)d_in[5];
    const float* bq    = (const float*)d_in[6];
    const float* Wk    = (const float*)d_in[7];
    const float* bk    = (const float*)d_in[8];
    const float* Wv    = (const float*)d_in[9];
    const float* bv    = (const float*)d_in[10];
    const float* Wo    = (const float*)d_in[11];
    const float* bo    = (const float*)d_in[12];
    const float* ln2_g = (const float*)d_in[13];
    const float* ln2_b = (const float*)d_in[14];
    const float* W1    = (const float*)d_in[15];
    const float* b1    = (const float*)d_in[16];
    const float* W2    = (const float*)d_in[17];
    const float* b2    = (const float*)d_in[18];
    const float* lno_g = (const float*)d_in[19];
    const float* lno_b = (const float*)d_in[20];
    float* out = (float*)d_out;

    float *e, *q, *k, *v, *ctx, *hbuf;
    cudaGetSymbolAddress((void**)&e,    g_e);
    cudaGetSymbolAddress((void**)&q,    g_q);
    cudaGetSymbolAddress((void**)&k,    g_k);
    cudaGetSymbolAddress((void**)&v,    g_v);
    cudaGetSymbolAddress((void**)&ctx,  g_ctx);
    cudaGetSymbolAddress((void**)&hbuf, g_h);

    const int M = TOK;
    dim3 g512(NU / 128, M / 128);     // (4, 64)
    dim3 g2048(EU / 128, M / 128);    // (16, 64)
    dim3 gattn(SEQ / 8, HEADS, NBATCH);

    // input projection: e = x @ Win^T + bin
    gemm_kernel<false, false><<<g512, 256>>>(x, Win, bin, nullptr, e, M, NU, IDIM);

    for (int i = 0; i < NLAYERS; i++) {
        const size_t wo = (size_t)i * NU * NU;
        const size_t w1o = (size_t)i * EU * NU;

        ln_kernel<<<M, 128>>>(e, ln1_g + i * NU, ln1_b + i * NU, e);

        gemm_kernel<false, false><<<g512, 256>>>(e, Wq + wo, bq + i * NU, nullptr, q, M, NU, NU);
        gemm_kernel<false, false><<<g512, 256>>>(e, Wk + wo, bk + i * NU, nullptr, k, M, NU, NU);
        gemm_kernel<false, false><<<g512, 256>>>(e, Wv + wo, bv + i * NU, nullptr, v, M, NU, NU);

        attn_kernel<<<gattn, 128>>>(q, k, v, ctx);

        // e = e + ctx @ Wo^T + bo
        gemm_kernel<false, true><<<g512, 256>>>(ctx, Wo + wo, bo + i * NU, e, e, M, NU, NU);

        ln_kernel<<<M, 128>>>(e, ln2_g + i * NU, ln2_b + i * NU, e);

        // hdn = relu(e @ W1^T + b1)
        gemm_kernel<true, false><<<g2048, 256>>>(e, W1 + w1o, b1 + (size_t)i * EU, nullptr, hbuf, M, EU, NU);
        // e = e + hdn @ W2^T + b2
        gemm_kernel<false, true><<<g512, 256>>>(hbuf, W2 + w1o, b2 + i * NU, e, e, M, NU, EU);
    }

    ln_kernel<<<M, 128>>>(e, lno_g, lno_b, out);
}

// round 2
// speedup vs baseline: 1.0011x; 1.0011x over previous
#include <cuda_runtime.h>
#include <cuda_bf16.h>
#include <math.h>

// ---------------------------------------------------------------------------
// Problem constants
// ---------------------------------------------------------------------------
#define TOK      8192       // B*T tokens (4*2*1024)
#define IDIM     256
#define NU       512        // N_UNITS
#define EU       2048       // E_UNITS
#define NLAYERS  4
#define HEADS    8
#define DK       64
#define SEQ      1024
#define NBATCH   8          // bs*num

// ---------------------------------------------------------------------------
// Scratch (static device memory; allocation APIs are forbidden)
// ---------------------------------------------------------------------------
__device__ float g_e  [TOK * NU];
__device__ float g_q  [TOK * NU];
__device__ float g_k  [TOK * NU];
__device__ float g_v  [TOK * NU];
__device__ float g_ctx[TOK * NU];
__device__ float g_h  [TOK * EU];

// ---------------------------------------------------------------------------
// GEMM: C[M,N] = A[M,K] @ W[N,K]^T + bias (+ optional ReLU, + optional residual)
// 128x128 block tile, 16 K-slab, 8x8 register micro-tile, 256 threads.
// M,N,K are all multiples of the tile sizes for every call in this problem.
// ---------------------------------------------------------------------------
template<bool RELU, bool RES>
__global__ __launch_bounds__(256) void gemm_kernel(
    const float* __restrict__ A, const float* __restrict__ W,
    const float* __restrict__ bias, const float* __restrict__ res,
    float* __restrict__ C, int M, int N, int K)
{
    __shared__ float As[16][128];
    __shared__ float Ws[16][128];

    const int tid = threadIdx.x;
    const int tx  = tid & 15;        // 0..15 -> N direction
    const int ty  = tid >> 4;        // 0..15 -> M direction
    const int n0  = blockIdx.x * 128;
    const int m0  = blockIdx.y * 128;

    const float* Ap = A + (size_t)m0 * K;
    const float* Wp = W + (size_t)n0 * K;

    float acc[8][8];
#pragma unroll
    for (int i = 0; i < 8; i++)
#pragma unroll
        for (int j = 0; j < 8; j++) acc[i][j] = 0.0f;

    for (int k0 = 0; k0 < K; k0 += 16) {
        // cooperative load: 128x16 tiles of A and W, stored K-transposed
#pragma unroll
        for (int i = 0; i < 2; i++) {
            int idx = tid + i * 256;          // 0..511
            int r   = idx >> 2;               // 0..127
            int c4  = (idx & 3) * 4;          // 0,4,8,12
            float4 va = *(const float4*)(Ap + (size_t)r * K + k0 + c4);
            As[c4 + 0][r] = va.x; As[c4 + 1][r] = va.y;
            As[c4 + 2][r] = va.z; As[c4 + 3][r] = va.w;
            float4 vw = *(const float4*)(Wp + (size_t)r * K + k0 + c4);
            Ws[c4 + 0][r] = vw.x; Ws[c4 + 1][r] = vw.y;
            Ws[c4 + 2][r] = vw.z; Ws[c4 + 3][r] = vw.w;
        }
        __syncthreads();

#pragma unroll
        for (int kk = 0; kk < 16; kk++) {
            float a[8], b[8];
            *(float4*)&a[0] = *(const float4*)&As[kk][ty * 8];
            *(float4*)&a[4] = *(const float4*)&As[kk][ty * 8 + 4];
            *(float4*)&b[0] = *(const float4*)&Ws[kk][tx * 8];
            *(float4*)&b[4] = *(const float4*)&Ws[kk][tx * 8 + 4];
#pragma unroll
            for (int i = 0; i < 8; i++)
#pragma unroll
                for (int j = 0; j < 8; j++)
                    acc[i][j] += a[i] * b[j];
        }
        __syncthreads();
    }

    // epilogue
#pragma unroll
    for (int i = 0; i < 8; i++) {
        int m = m0 + ty * 8 + i;
#pragma unroll
        for (int j = 0; j < 8; j += 4) {
            int n = n0 + tx * 8 + j;
            float4 bv = *(const float4*)(bias + n);
            float4 o;
            o.x = acc[i][j + 0] + bv.x;
            o.y = acc[i][j + 1] + bv.y;
            o.z = acc[i][j + 2] + bv.z;
            o.w = acc[i][j + 3] + bv.w;
            if (RELU) {
                o.x = fmaxf(o.x, 0.0f); o.y = fmaxf(o.y, 0.0f);
                o.z = fmaxf(o.z, 0.0f); o.w = fmaxf(o.w, 0.0f);
            }
            if (RES) {
                float4 rv = *(const float4*)(res + (size_t)m * N + n);
                o.x += rv.x; o.y += rv.y; o.z += rv.z; o.w += rv.w;
            }
            *(float4*)(C + (size_t)m * N + n) = o;
        }
    }
}

// ---------------------------------------------------------------------------
// LayerNorm over rows of 512 (works in-place). 128 threads, float4 per thread.
// ---------------------------------------------------------------------------
__global__ __launch_bounds__(128) void ln_kernel(
    const float* __restrict__ X, const float* __restrict__ gamma,
    const float* __restrict__ beta, float* __restrict__ O)
{
    __shared__ float red[4];
    const int row = blockIdx.x;
    const int tid = threadIdx.x;

    float4 v = *(const float4*)(X + (size_t)row * NU + tid * 4);
    float s = v.x + v.y + v.z + v.w;
#pragma unroll
    for (int o = 16; o > 0; o >>= 1) s += __shfl_xor_sync(0xffffffffu, s, o);
    if ((tid & 31) == 0) red[tid >> 5] = s;
    __syncthreads();
    float mean = (red[0] + red[1] + red[2] + red[3]) * (1.0f / 512.0f);
    __syncthreads();

    float dx = v.x - mean, dy = v.y - mean, dz = v.z - mean, dw = v.w - mean;
    float sq = dx * dx + dy * dy + dz * dz + dw * dw;
#pragma unroll
    for (int o = 16; o > 0; o >>= 1) sq += __shfl_xor_sync(0xffffffffu, sq, o);
    if ((tid & 31) == 0) red[tid >> 5] = sq;
    __syncthreads();
    float var = (red[0] + red[1] + red[2] + red[3]) * (1.0f / 512.0f);
    float inv = rsqrtf(var + 1e-5f);

    float4 g = *(const float4*)(gamma + tid * 4);
    float4 b = *(const float4*)(beta  + tid * 4);
    float4 o4;
    o4.x = dx * inv * g.x + b.x;
    o4.y = dy * inv * g.y + b.y;
    o4.z = dz * inv * g.z + b.z;
    o4.w = dw * inv * g.w + b.w;
    *(float4*)(O + (size_t)row * NU + tid * 4) = o4;
}

// ---------------------------------------------------------------------------
// Attention: one block handles 8 query rows of one (b,h).
// Full 1024-wide score rows held in smem; K/V streamed in 32-row tiles.
// ---------------------------------------------------------------------------
__global__ __launch_bounds__(128) void attn_kernel(
    const float* __restrict__ Q, const float* __restrict__ K,
    const float* __restrict__ V, float* __restrict__ O)
{
    __shared__ float Ss[8][1024];     // scores / probs
    __shared__ float KVs[32][68];     // K or V tile (padded rows)
    __shared__ float rowsum[8];

    const int tid = threadIdx.x;
    const int qt = blockIdx.x;        // 0..127 (query tile of 8)
    const int h  = blockIdx.y;        // 0..7
    const int b  = blockIdx.z;        // 0..7
    const int qr = tid >> 4;          // 0..7  thread's query row
    const int sl = tid & 15;

    const size_t base = ((size_t)b * SEQ) * NU + (size_t)h * DK;

    // this thread's query row in registers (16 x float4 = 64 floats)
    float4 qreg[16];
    {
        const float* qp = Q + base + (size_t)(qt * 8 + qr) * NU;
#pragma unroll
        for (int i = 0; i < 16; i++) qreg[i] = *(const float4*)(qp + i * 4);
    }

    // ---- phase 1: scores = Q K^T * scale ----
    for (int st = 0; st < 32; st++) {
        int s0 = st * 32;
#pragma unroll
        for (int i = 0; i < 4; i++) {
            int idx = tid + i * 128;          // 0..511
            int r   = idx >> 4;               // 0..31
            int c4  = (idx & 15) * 4;         // 0..60
            *(float4*)&KVs[r][c4] =
                *(const float4*)(K + base + (size_t)(s0 + r) * NU + c4);
        }
        __syncthreads();
#pragma unroll
        for (int ss = 0; ss < 2; ss++) {
            int s = sl + ss * 16;
            float a = 0.0f;
#pragma unroll
            for (int i = 0; i < 16; i++) {
                float4 kk = *(const float4*)&KVs[s][i * 4];
                a += qreg[i].x * kk.x + qreg[i].y * kk.y
                   + qreg[i].z * kk.z + qreg[i].w * kk.w;
            }
            Ss[qr][s0 + s] = a * 0.125f;     // 1/sqrt(64)
        }
        __syncthreads();
    }

    // ---- phase 2: softmax (unnormalized; keep row sums) ----
    {
        const int warp = tid >> 5, lane = tid & 31;
        for (int r = warp; r < 8; r += 4) {
            float m = -1e30f;
            for (int j = lane; j < 1024; j += 32) m = fmaxf(m, Ss[r][j]);
#pragma unroll
            for (int o = 16; o > 0; o >>= 1)
                m = fmaxf(m, __shfl_xor_sync(0xffffffffu, m, o));
            float sum = 0.0f;
            for (int j = lane; j < 1024; j += 32) {
                float p = __expf(Ss[r][j] - m);
                Ss[r][j] = p;
                sum += p;
            }
#pragma unroll
            for (int o = 16; o > 0; o >>= 1)
                sum += __shfl_xor_sync(0xffffffffu, sum, o);
            if (lane == 0) rowsum[r] = sum;
        }
    }
    __syncthreads();

    // ---- phase 3: ctx = P V ----
    const int d0 = (tid & 15) * 4;
    float4 acc = make_float4(0.f, 0.f, 0.f, 0.f);
    for (int st = 0; st < 32; st++) {
        int s0 = st * 32;
#pragma unroll
        for (int i = 0; i < 4; i++) {
            int idx = tid + i * 128;
            int r   = idx >> 4;
            int c4  = (idx & 15) * 4;
            *(float4*)&KVs[r][c4] =
                *(const float4*)(V + base + (size_t)(s0 + r) * NU + c4);
        }
        __syncthreads();
#pragma unroll
        for (int s = 0; s < 32; s++) {
            float p = Ss[qr][s0 + s];
            float4 vv = *(const float4*)&KVs[s][d0];
            acc.x += p * vv.x; acc.y += p * vv.y;
            acc.z += p * vv.z; acc.w += p * vv.w;
        }
        __syncthreads();
    }

    float inv = 1.0f / rowsum[qr];
    float4 o4 = make_float4(acc.x * inv, acc.y * inv, acc.z * inv, acc.w * inv);
    *(float4*)(O + base + (size_t)(qt * 8 + qr) * NU + d0) = o4;
}

// ---------------------------------------------------------------------------
// Host orchestration (graph-capturable: kernel launches only)
// ---------------------------------------------------------------------------
extern "C" void kernel_launch(void* const* d_in, const int* in_sizes, int n_in,
                              void* d_out, int out_size)
{
    (void)in_sizes; (void)n_in; (void)out_size;

    const float* x     = (const float*)d_in[0];
    const float* Win   = (const float*)d_in[1];
    const float* bin   = (const float*)d_in[2];
    const float* ln1_g = (const float*)d_in[3];
    const float* ln1_b = (const float*)d_in[4];
    const float* Wq    = (const float*)d_in[5];
    const float* bq    = (const float*)d_in[6];
    const float* Wk    = (const float*)d_in[7];
    const float* bk    = (const float*)d_in[8];
    const float* Wv    = (const float*)d_in[9];
    const float* bv    = (const float*)d_in[10];
    const float* Wo    = (const float*)d_in[11];
    const float* bo    = (const float*)d_in[12];
    const float* ln2_g = (const float*)d_in[13];
    const float* ln2_b = (const float*)d_in[14];
    const float* W1    = (const float*)d_in[15];
    const float* b1    = (const float*)d_in[16];
    const float* W2    = (const float*)d_in[17];
    const float* b2    = (const float*)d_in[18];
    const float* lno_g = (const float*)d_in[19];
    const float* lno_b = (const float*)d_in[20];
    float* out = (float*)d_out;

    float *e, *q, *k, *v, *ctx, *hbuf;
    cudaGetSymbolAddress((void**)&e,    g_e);
    cudaGetSymbolAddress((void**)&q,    g_q);
    cudaGetSymbolAddress((void**)&k,    g_k);
    cudaGetSymbolAddress((void**)&v,    g_v);
    cudaGetSymbolAddress((void**)&ctx,  g_ctx);
    cudaGetSymbolAddress((void**)&hbuf, g_h);

    const int M = TOK;
    dim3 g512(NU / 128, M / 128);     // (4, 64)
    dim3 g2048(EU / 128, M / 128);    // (16, 64)
    dim3 gattn(SEQ / 8, HEADS, NBATCH);

    // input projection: e = x @ Win^T + bin
    gemm_kernel<false, false><<<g512, 256>>>(x, Win, bin, nullptr, e, M, NU, IDIM);

    for (int i = 0; i < NLAYERS; i++) {
        const size_t wo = (size_t)i * NU * NU;
        const size_t w1o = (size_t)i * EU * NU;

        ln_kernel<<<M, 128>>>(e, ln1_g + i * NU, ln1_b + i * NU, e);

        gemm_kernel<false, false><<<g512, 256>>>(e, Wq + wo, bq + i * NU, nullptr, q, M, NU, NU);
        gemm_kernel<false, false><<<g512, 256>>>(e, Wk + wo, bk + i * NU, nullptr, k, M, NU, NU);
        gemm_kernel<false, false><<<g512, 256>>>(e, Wv + wo, bv + i * NU, nullptr, v, M, NU, NU);

        attn_kernel<<<gattn, 128>>>(q, k, v, ctx);

        // e = e + ctx @ Wo^T + bo
        gemm_kernel<false, true><<<g512, 256>>>(ctx, Wo + wo, bo + i * NU, e, e, M, NU, NU);

        ln_kernel<<<M, 128>>>(e, ln2_g + i * NU, ln2_b + i * NU, e);

        // hdn = relu(e @ W1^T + b1)
        gemm_kernel<true, false><<<g2048, 256>>>(e, W1 + w1o, b1 + (size_t)i * EU, nullptr, hbuf, M, EU, NU);
        // e = e + hdn @ W2^T + b2
        gemm_kernel<false, true><<<g512, 256>>>(hbuf, W2 + w1o, b2 + i * NU, e, e, M, NU, EU);
    }

    ln_kernel<<<M, 128>>>(e, lno_g, lno_b, out);
}

// round 3
// speedup vs baseline: 1.0012x; 1.0001x over previous
#include <cuda_runtime.h>
#include <cuda_bf16.h>
#include <math.h>

// ---------------------------------------------------------------------------
// Problem constants
// ---------------------------------------------------------------------------
#define TOK      8192       // B*T tokens (4*2*1024)
#define IDIM     256
#define NU       512        // N_UNITS
#define EU       2048       // E_UNITS
#define NLAYERS  4
#define HEADS    8
#define DK       64
#define SEQ      1024
#define NBATCH   8          // bs*num

// ---------------------------------------------------------------------------
// Scratch (static device memory; allocation APIs are forbidden)
// ---------------------------------------------------------------------------
__device__ float g_e  [TOK * NU];
__device__ float g_q  [TOK * NU];
__device__ float g_k  [TOK * NU];
__device__ float g_v  [TOK * NU];
__device__ float g_ctx[TOK * NU];
__device__ float g_h  [TOK * EU];

// ---------------------------------------------------------------------------
// GEMM: C[M,N] = A[M,K] @ W[N,K]^T + bias (+ optional ReLU, + optional residual)
// 128x128 block tile, 16 K-slab, 8x8 register micro-tile, 256 threads.
// M,N,K are all multiples of the tile sizes for every call in this problem.
// ---------------------------------------------------------------------------
template<bool RELU, bool RES>
__global__ __launch_bounds__(256) void gemm_kernel(
    const float* __restrict__ A, const float* __restrict__ W,
    const float* __restrict__ bias, const float* __restrict__ res,
    float* __restrict__ C, int M, int N, int K)
{
    __shared__ float As[16][128];
    __shared__ float Ws[16][128];

    const int tid = threadIdx.x;
    const int tx  = tid & 15;        // 0..15 -> N direction
    const int ty  = tid >> 4;        // 0..15 -> M direction
    const int n0  = blockIdx.x * 128;
    const int m0  = blockIdx.y * 128;

    const float* Ap = A + (size_t)m0 * K;
    const float* Wp = W + (size_t)n0 * K;

    float acc[8][8];
#pragma unroll
    for (int i = 0; i < 8; i++)
#pragma unroll
        for (int j = 0; j < 8; j++) acc[i][j] = 0.0f;

    for (int k0 = 0; k0 < K; k0 += 16) {
        // cooperative load: 128x16 tiles of A and W, stored K-transposed
#pragma unroll
        for (int i = 0; i < 2; i++) {
            int idx = tid + i * 256;          // 0..511
            int r   = idx >> 2;               // 0..127
            int c4  = (idx & 3) * 4;          // 0,4,8,12
            float4 va = *(const float4*)(Ap + (size_t)r * K + k0 + c4);
            As[c4 + 0][r] = va.x; As[c4 + 1][r] = va.y;
            As[c4 + 2][r] = va.z; As[c4 + 3][r] = va.w;
            float4 vw = *(const float4*)(Wp + (size_t)r * K + k0 + c4);
            Ws[c4 + 0][r] = vw.x; Ws[c4 + 1][r] = vw.y;
            Ws[c4 + 2][r] = vw.z; Ws[c4 + 3][r] = vw.w;
        }
        __syncthreads();

#pragma unroll
        for (int kk = 0; kk < 16; kk++) {
            float a[8], b[8];
            *(float4*)&a[0] = *(const float4*)&As[kk][ty * 8];
            *(float4*)&a[4] = *(const float4*)&As[kk][ty * 8 + 4];
            *(float4*)&b[0] = *(const float4*)&Ws[kk][tx * 8];
            *(float4*)&b[4] = *(const float4*)&Ws[kk][tx * 8 + 4];
#pragma unroll
            for (int i = 0; i < 8; i++)
#pragma unroll
                for (int j = 0; j < 8; j++)
                    acc[i][j] += a[i] * b[j];
        }
        __syncthreads();
    }

    // epilogue
#pragma unroll
    for (int i = 0; i < 8; i++) {
        int m = m0 + ty * 8 + i;
#pragma unroll
        for (int j = 0; j < 8; j += 4) {
            int n = n0 + tx * 8 + j;
            float4 bv = *(const float4*)(bias + n);
            float4 o;
            o.x = acc[i][j + 0] + bv.x;
            o.y = acc[i][j + 1] + bv.y;
            o.z = acc[i][j + 2] + bv.z;
            o.w = acc[i][j + 3] + bv.w;
            if (RELU) {
                o.x = fmaxf(o.x, 0.0f); o.y = fmaxf(o.y, 0.0f);
                o.z = fmaxf(o.z, 0.0f); o.w = fmaxf(o.w, 0.0f);
            }
            if (RES) {
                float4 rv = *(const float4*)(res + (size_t)m * N + n);
                o.x += rv.x; o.y += rv.y; o.z += rv.z; o.w += rv.w;
            }
            *(float4*)(C + (size_t)m * N + n) = o;
        }
    }
}

// ---------------------------------------------------------------------------
// LayerNorm over rows of 512 (works in-place). 128 threads, float4 per thread.
// ---------------------------------------------------------------------------
__global__ __launch_bounds__(128) void ln_kernel(
    const float* __restrict__ X, const float* __restrict__ gamma,
    const float* __restrict__ beta, float* __restrict__ O)
{
    __shared__ float red[4];
    const int row = blockIdx.x;
    const int tid = threadIdx.x;

    float4 v = *(const float4*)(X + (size_t)row * NU + tid * 4);
    float s = v.x + v.y + v.z + v.w;
#pragma unroll
    for (int o = 16; o > 0; o >>= 1) s += __shfl_xor_sync(0xffffffffu, s, o);
    if ((tid & 31) == 0) red[tid >> 5] = s;
    __syncthreads();
    float mean = (red[0] + red[1] + red[2] + red[3]) * (1.0f / 512.0f);
    __syncthreads();

    float dx = v.x - mean, dy = v.y - mean, dz = v.z - mean, dw = v.w - mean;
    float sq = dx * dx + dy * dy + dz * dz + dw * dw;
#pragma unroll
    for (int o = 16; o > 0; o >>= 1) sq += __shfl_xor_sync(0xffffffffu, sq, o);
    if ((tid & 31) == 0) red[tid >> 5] = sq;
    __syncthreads();
    float var = (red[0] + red[1] + red[2] + red[3]) * (1.0f / 512.0f);
    float inv = rsqrtf(var + 1e-5f);

    float4 g = *(const float4*)(gamma + tid * 4);
    float4 b = *(const float4*)(beta  + tid * 4);
    float4 o4;
    o4.x = dx * inv * g.x + b.x;
    o4.y = dy * inv * g.y + b.y;
    o4.z = dz * inv * g.z + b.z;
    o4.w = dw * inv * g.w + b.w;
    *(float4*)(O + (size_t)row * NU + tid * 4) = o4;
}

// ---------------------------------------------------------------------------
// Attention: one block handles 8 query rows of one (b,h).
// Full 1024-wide score rows held in smem; K/V streamed in 32-row tiles.
// ---------------------------------------------------------------------------
__global__ __launch_bounds__(128) void attn_kernel(
    const float* __restrict__ Q, const float* __restrict__ K,
    const float* __restrict__ V, float* __restrict__ O)
{
    __shared__ float Ss[8][1024];     // scores / probs
    __shared__ float KVs[32][68];     // K or V tile (padded rows)
    __shared__ float rowsum[8];

    const int tid = threadIdx.x;
    const int qt = blockIdx.x;        // 0..127 (query tile of 8)
    const int h  = blockIdx.y;        // 0..7
    const int b  = blockIdx.z;        // 0..7
    const int qr = tid >> 4;          // 0..7  thread's query row
    const int sl = tid & 15;

    const size_t base = ((size_t)b * SEQ) * NU + (size_t)h * DK;

    // this thread's query row in registers (16 x float4 = 64 floats)
    float4 qreg[16];
    {
        const float* qp = Q + base + (size_t)(qt * 8 + qr) * NU;
#pragma unroll
        for (int i = 0; i < 16; i++) qreg[i] = *(const float4*)(qp + i * 4);
    }

    // ---- phase 1: scores = Q K^T * scale ----
    for (int st = 0; st < 32; st++) {
        int s0 = st * 32;
#pragma unroll
        for (int i = 0; i < 4; i++) {
            int idx = tid + i * 128;          // 0..511
            int r   = idx >> 4;               // 0..31
            int c4  = (idx & 15) * 4;         // 0..60
            *(float4*)&KVs[r][c4] =
                *(const float4*)(K + base + (size_t)(s0 + r) * NU + c4);
        }
        __syncthreads();
#pragma unroll
        for (int ss = 0; ss < 2; ss++) {
            int s = sl + ss * 16;
            float a = 0.0f;
#pragma unroll
            for (int i = 0; i < 16; i++) {
                float4 kk = *(const float4*)&KVs[s][i * 4];
                a += qreg[i].x * kk.x + qreg[i].y * kk.y
                   + qreg[i].z * kk.z + qreg[i].w * kk.w;
            }
            Ss[qr][s0 + s] = a * 0.125f;     // 1/sqrt(64)
        }
        __syncthreads();
    }

    // ---- phase 2: softmax (unnormalized; keep row sums) ----
    {
        const int warp = tid >> 5, lane = tid & 31;
        for (int r = warp; r < 8; r += 4) {
            float m = -1e30f;
            for (int j = lane; j < 1024; j += 32) m = fmaxf(m, Ss[r][j]);
#pragma unroll
            for (int o = 16; o > 0; o >>= 1)
                m = fmaxf(m, __shfl_xor_sync(0xffffffffu, m, o));
            float sum = 0.0f;
            for (int j = lane; j < 1024; j += 32) {
                float p = __expf(Ss[r][j] - m);
                Ss[r][j] = p;
                sum += p;
            }
#pragma unroll
            for (int o = 16; o > 0; o >>= 1)
                sum += __shfl_xor_sync(0xffffffffu, sum, o);
            if (lane == 0) rowsum[r] = sum;
        }
    }
    __syncthreads();

    // ---- phase 3: ctx = P V ----
    const int d0 = (tid & 15) * 4;
    float4 acc = make_float4(0.f, 0.f, 0.f, 0.f);
    for (int st = 0; st < 32; st++) {
        int s0 = st * 32;
#pragma unroll
        for (int i = 0; i < 4; i++) {
            int idx = tid + i * 128;
            int r   = idx >> 4;
            int c4  = (idx & 15) * 4;
            *(float4*)&KVs[r][c4] =
                *(const float4*)(V + base + (size_t)(s0 + r) * NU + c4);
        }
        __syncthreads();
#pragma unroll
        for (int s = 0; s < 32; s++) {
            float p = Ss[qr][s0 + s];
            float4 vv = *(const float4*)&KVs[s][d0];
            acc.x += p * vv.x; acc.y += p * vv.y;
            acc.z += p * vv.z; acc.w += p * vv.w;
        }
        __syncthreads();
    }

    float inv = 1.0f / rowsum[qr];
    float4 o4 = make_float4(acc.x * inv, acc.y * inv, acc.z * inv, acc.w * inv);
    *(float4*)(O + base + (size_t)(qt * 8 + qr) * NU + d0) = o4;
}

// ---------------------------------------------------------------------------
// Host orchestration (graph-capturable: kernel launches only)
// ---------------------------------------------------------------------------
extern "C" void kernel_launch(void* const* d_in, const int* in_sizes, int n_in,
                              void* d_out, int out_size)
{
    (void)in_sizes; (void)n_in; (void)out_size;

    const float* x     = (const float*)d_in[0];
    const float* Win   = (const float*)d_in[1];
    const float* bin   = (const float*)d_in[2];
    const float* ln1_g = (const float*)d_in[3];
    const float* ln1_b = (const float*)d_in[4];
    const float* Wq    = (const float*)d_in[5];
    const float* bq    = (const float*)d_in[6];
    const float* Wk    = (const float*)d_in[7];
    const float* bk    = (const float*)d_in[8];
    const float* Wv    = (const float*)d_in[9];
    const float* bv    = (const float*)d_in[10];
    const float* Wo    = (const float*)d_in[11];
    const float* bo    = (const float*)d_in[12];
    const float* ln2_g = (const float*)d_in[13];
    const float* ln2_b = (const float*)d_in[14];
    const float* W1    = (const float*)d_in[15];
    const float* b1    = (const float*)d_in[16];
    const float* W2    = (const float*)d_in[17];
    const float* b2    = (const float*)d_in[18];
    const float* lno_g = (const float*)d_in[19];
    const float* lno_b = (const float*)d_in[20];
    float* out = (float*)d_out;

    float *e, *q, *k, *v, *ctx, *hbuf;
    cudaGetSymbolAddress((void**)&e,    g_e);
    cudaGetSymbolAddress((void**)&q,    g_q);
    cudaGetSymbolAddress((void**)&k,    g_k);
    cudaGetSymbolAddress((void**)&v,    g_v);
    cudaGetSymbolAddress((void**)&ctx,  g_ctx);
    cudaGetSymbolAddress((void**)&hbuf, g_h);

    const int M = TOK;
    dim3 g512(NU / 128, M / 128);     // (4, 64)
    dim3 g2048(EU / 128, M / 128);    // (16, 64)
    dim3 gattn(SEQ / 8, HEADS, NBATCH);

    // input projection: e = x @ Win^T + bin
    gemm_kernel<false, false><<<g512, 256>>>(x, Win, bin, nullptr, e, M, NU, IDIM);

    for (int i = 0; i < NLAYERS; i++) {
        const size_t wo = (size_t)i * NU * NU;
        const size_t w1o = (size_t)i * EU * NU;

        ln_kernel<<<M, 128>>>(e, ln1_g + i * NU, ln1_b + i * NU, e);

        gemm_kernel<false, false><<<g512, 256>>>(e, Wq + wo, bq + i * NU, nullptr, q, M, NU, NU);
        gemm_kernel<false, false><<<g512, 256>>>(e, Wk + wo, bk + i * NU, nullptr, k, M, NU, NU);
        gemm_kernel<false, false><<<g512, 256>>>(e, Wv + wo, bv + i * NU, nullptr, v, M, NU, NU);

        attn_kernel<<<gattn, 128>>>(q, k, v, ctx);

        // e = e + ctx @ Wo^T + bo
        gemm_kernel<false, true><<<g512, 256>>>(ctx, Wo + wo, bo + i * NU, e, e, M, NU, NU);

        ln_kernel<<<M, 128>>>(e, ln2_g + i * NU, ln2_b + i * NU, e);

        // hdn = relu(e @ W1^T + b1)
        gemm_kernel<true, false><<<g2048, 256>>>(e, W1 + w1o, b1 + (size_t)i * EU, nullptr, hbuf, M, EU, NU);
        // e = e + hdn @ W2^T + b2
        gemm_kernel<false, true><<<g512, 256>>>(hbuf, W2 + w1o, b2 + i * NU, e, e, M, NU, EU);
    }

    ln_kernel<<<M, 128>>>(e, lno_g, lno_b, out);
}